// round 13
// baseline (speedup 1.0000x reference)
#include <cuda_runtime.h>

#define N_MAX 50000
#define E_MAX 800000
#define IN_FEATS 128
#define HF 64

// Scratch (device globals; no allocation allowed)
__device__ int   g_cnt[N_MAX];
__device__ int   g_off[N_MAX + 1];
__device__ int   g_cur[N_MAX];
__device__ int   g_bsum[256];
__device__ int   g_esrc[E_MAX];
__device__ float g_dinv[N_MAX];
__device__ float g_x[N_MAX * HF];
__device__ float g_f1[N_MAX * HF];
__device__ float g_f2[N_MAX * HF];
__device__ float g_M[HF * 192];

// ---------------------------------------------------------------------------
__global__ void count_kernel(const int* __restrict__ dst, int e) {
    int i = blockIdx.x * blockDim.x + threadIdx.x;
    if (i < e) atomicAdd(&g_cnt[dst[i]], 1);
}

__global__ void scan1_kernel(int n) {
    __shared__ int sh[256];
    int t = threadIdx.x;
    int i = blockIdx.x * 256 + t;
    int v = (i < n) ? g_cnt[i] : 0;
    sh[t] = v;
    __syncthreads();
#pragma unroll
    for (int o = 1; o < 256; o <<= 1) {
        int add = (t >= o) ? sh[t - o] : 0;
        __syncthreads();
        sh[t] += add;
        __syncthreads();
    }
    if (i < n) g_off[i] = sh[t] - v;
    if (t == 255) g_bsum[blockIdx.x] = sh[255];
}

__global__ void scan3_kernel(int n, int e, int nb) {
    __shared__ int sh[256];
    int t = threadIdx.x;
    sh[t] = (t < nb) ? g_bsum[t] : 0;
    __syncthreads();
#pragma unroll
    for (int o = 1; o < 256; o <<= 1) {
        int add = (t >= o) ? sh[t - o] : 0;
        __syncthreads();
        sh[t] += add;
        __syncthreads();
    }
    int boff = (blockIdx.x == 0) ? 0 : sh[blockIdx.x - 1];
    int i = blockIdx.x * 256 + t;
    if (i < n) {
        int o = g_off[i] + boff;
        g_off[i] = o;
        g_cur[i] = o;
        g_dinv[i] = rsqrtf(fmaxf((float)g_cnt[i], 1.0f));
    }
    if (i == 0) g_off[n] = e;
}

__global__ void fill_kernel(const int* __restrict__ src,
                            const int* __restrict__ dst, int e) {
    int i = blockIdx.x * blockDim.x + threadIdx.x;
    if (i < e) {
        int d = dst[i];
        int pos = atomicAdd(&g_cur[d], 1);
        g_esrc[pos] = src[i];
    }
}

// ---------------------------------------------------------------------------
// Gather SpMM over node range [base, base+cnt)  (inner loop unchanged)
__global__ __launch_bounds__(256) void spmm_kernel(int base, int cnt, int step) {
    const float* fin = (step == 0) ? g_x : g_f1;
    float* fout      = (step == 0) ? g_f1 : g_f2;
    int wi = (blockIdx.x * blockDim.x + threadIdx.x) >> 5;
    int lane = threadIdx.x & 31;
    if (wi >= cnt) return;
    int w = base + wi;
    int c = lane & 15;
    int pair = lane >> 4;
    int beg = g_off[w];
    int end = g_off[w + 1];
    const float4* F4 = reinterpret_cast<const float4*>(fin);
    float4 acc = make_float4(0.f, 0.f, 0.f, 0.f);

    int j = beg + pair;
    int s_next = (j < end) ? __ldg(&g_esrc[j]) : 0;
    while (j < end) {
        int s = s_next;
        int jn = j + 2;
        if (jn < end) s_next = __ldg(&g_esrc[jn]);
        float wt = __ldg(&g_dinv[s]);
        float4 v = F4[(size_t)s * 16 + c];
        acc.x = fmaf(wt, v.x, acc.x);
        acc.y = fmaf(wt, v.y, acc.y);
        acc.z = fmaf(wt, v.z, acc.z);
        acc.w = fmaf(wt, v.w, acc.w);
        j = jn;
    }

    acc.x += __shfl_xor_sync(0xffffffffu, acc.x, 16);
    acc.y += __shfl_xor_sync(0xffffffffu, acc.y, 16);
    acc.z += __shfl_xor_sync(0xffffffffu, acc.z, 16);
    acc.w += __shfl_xor_sync(0xffffffffu, acc.w, 16);

    if (pair == 0) {
        float wd = g_dinv[w];
        float4 xv = F4[(size_t)w * 16 + c];
        float4 r = make_float4(xv.x - wd * acc.x, xv.y - wd * acc.y,
                               xv.z - wd * acc.z, xv.w - wd * acc.w);
        reinterpret_cast<float4*>(fout)[(size_t)w * 16 + c] = r;
    }
}

// ---------------------------------------------------------------------------
// GEMM1 (best-measured version, unchanged)
__global__ __launch_bounds__(256) void gemm1_kernel(
    const float* __restrict__ A, const float* __restrict__ W1,
    const float* __restrict__ b1, int n) {
    __shared__ float As[32][132];
    __shared__ float Bs[32][68];
    int t = threadIdx.x;
    int m0 = blockIdx.x * 128;
    int tx = t & 7, ty = t >> 3;
    int kv = t & 7, m4 = t >> 3;

    float acc[4][8];
#pragma unroll
    for (int i = 0; i < 4; i++)
#pragma unroll
        for (int j = 0; j < 8; j++) acc[i][j] = 0.f;

    for (int k0 = 0; k0 < IN_FEATS; k0 += 32) {
#pragma unroll
        for (int i = 0; i < 4; i++) {
            int m = m4 * 4 + i;
            int gm = m0 + m;
            float4 v = make_float4(0.f, 0.f, 0.f, 0.f);
            if (gm < n)
                v = *reinterpret_cast<const float4*>(A + (size_t)gm * IN_FEATS + k0 + kv * 4);
            As[kv * 4 + 0][m] = v.x;
            As[kv * 4 + 1][m] = v.y;
            As[kv * 4 + 2][m] = v.z;
            As[kv * 4 + 3][m] = v.w;
        }
#pragma unroll
        for (int i = 0; i < 2; i++) {
            int fl = t * 2 + i;
            int nn = fl >> 3, kv2 = fl & 7;
            float4 v = *reinterpret_cast<const float4*>(W1 + (size_t)nn * IN_FEATS + k0 + kv2 * 4);
            Bs[kv2 * 4 + 0][nn] = v.x;
            Bs[kv2 * 4 + 1][nn] = v.y;
            Bs[kv2 * 4 + 2][nn] = v.z;
            Bs[kv2 * 4 + 3][nn] = v.w;
        }
        __syncthreads();
#pragma unroll
        for (int k = 0; k < 32; k++) {
            float4 a = *reinterpret_cast<float4*>(&As[k][ty * 4]);
            float4 bA = *reinterpret_cast<float4*>(&Bs[k][tx * 8]);
            float4 bB = *reinterpret_cast<float4*>(&Bs[k][tx * 8 + 4]);
            float av[4] = {a.x, a.y, a.z, a.w};
            float bv[8] = {bA.x, bA.y, bA.z, bA.w, bB.x, bB.y, bB.z, bB.w};
#pragma unroll
            for (int i = 0; i < 4; i++)
#pragma unroll
                for (int j = 0; j < 8; j++)
                    acc[i][j] = fmaf(av[i], bv[j], acc[i][j]);
        }
        __syncthreads();
    }
#pragma unroll
    for (int i = 0; i < 4; i++) {
        int gm = m0 + ty * 4 + i;
        if (gm < n) {
#pragma unroll
            for (int j = 0; j < 8; j++) {
                float v = acc[i][j] + b1[tx * 8 + j];
                g_x[(size_t)gm * HF + tx * 8 + j] = v > 0.f ? v : 0.f;
            }
        }
    }
}

// ---------------------------------------------------------------------------
__global__ void buildM_kernel(const float* __restrict__ W2) {
    int t = blockIdx.x * blockDim.x + threadIdx.x;
    if (t >= HF * 192) return;
    int r = t / 192, k = t % 192;
    int p = k >> 6, c = k & 63;
    const float cA[3] = {3.0f, -3.0f, 0.75f};
    const float cB[3] = {0.0f, 3.0f, -1.5f};
    const float cC[3] = {0.0f, 0.0f, 0.75f};
    g_M[t] = cA[p] * W2[r * 192 + c]
           + cB[p] * W2[r * 192 + 64 + c]
           + cC[p] * W2[r * 192 + 128 + c];
}

// ---------------------------------------------------------------------------
// GEMM2 rank-64 pass over node range [base, base+cnt):
// pass 0: out = x*M0^T + b2;  pass 1: out += f1*M1^T;  pass 2: out += f2*M2^T
__global__ __launch_bounds__(256) void gemm2_pass_kernel(
    const float* __restrict__ b2, float* __restrict__ out,
    int base, int cnt, int pass) {
    __shared__ float As[32][132];
    __shared__ float Bs[32][68];
    int t = threadIdx.x;
    int m0 = base + blockIdx.x * 128;
    int mend = base + cnt;
    int tx = t & 7, ty = t >> 3;
    int kv = t & 7, m4 = t >> 3;
    const float* S = (pass == 0) ? g_x : (pass == 1) ? g_f1 : g_f2;

    float acc[4][8];
#pragma unroll
    for (int i = 0; i < 4; i++)
#pragma unroll
        for (int j = 0; j < 8; j++) acc[i][j] = 0.f;

#pragma unroll
    for (int cch = 0; cch < 2; cch++) {
        int koff = cch * 32;
#pragma unroll
        for (int i = 0; i < 4; i++) {
            int m = m4 * 4 + i;
            int gm = m0 + m;
            float4 v = make_float4(0.f, 0.f, 0.f, 0.f);
            if (gm < mend)
                v = *reinterpret_cast<const float4*>(S + (size_t)gm * HF + koff + kv * 4);
            As[kv * 4 + 0][m] = v.x;
            As[kv * 4 + 1][m] = v.y;
            As[kv * 4 + 2][m] = v.z;
            As[kv * 4 + 3][m] = v.w;
        }
#pragma unroll
        for (int i = 0; i < 2; i++) {
            int fl = t * 2 + i;
            int nn = fl >> 3, kv2 = fl & 7;
            float4 v = *reinterpret_cast<const float4*>(
                g_M + (size_t)nn * 192 + pass * 64 + koff + kv2 * 4);
            Bs[kv2 * 4 + 0][nn] = v.x;
            Bs[kv2 * 4 + 1][nn] = v.y;
            Bs[kv2 * 4 + 2][nn] = v.z;
            Bs[kv2 * 4 + 3][nn] = v.w;
        }
        __syncthreads();
#pragma unroll
        for (int k = 0; k < 32; k++) {
            float4 a = *reinterpret_cast<float4*>(&As[k][ty * 4]);
            float4 bA = *reinterpret_cast<float4*>(&Bs[k][tx * 8]);
            float4 bB = *reinterpret_cast<float4*>(&Bs[k][tx * 8 + 4]);
            float av[4] = {a.x, a.y, a.z, a.w};
            float bv[8] = {bA.x, bA.y, bA.z, bA.w, bB.x, bB.y, bB.z, bB.w};
#pragma unroll
            for (int i = 0; i < 4; i++)
#pragma unroll
                for (int j = 0; j < 8; j++)
                    acc[i][j] = fmaf(av[i], bv[j], acc[i][j]);
        }
        __syncthreads();
    }
#pragma unroll
    for (int i = 0; i < 4; i++) {
        int gm = m0 + ty * 4 + i;
        if (gm < mend) {
            float4* dst = reinterpret_cast<float4*>(&out[(size_t)gm * HF + tx * 8]);
            if (pass == 0) {
                float o[8];
#pragma unroll
                for (int j = 0; j < 8; j++) o[j] = acc[i][j] + b2[tx * 8 + j];
                dst[0] = make_float4(o[0], o[1], o[2], o[3]);
                dst[1] = make_float4(o[4], o[5], o[6], o[7]);
            } else {
                float4 p0 = dst[0], p1 = dst[1];
                dst[0] = make_float4(p0.x + acc[i][0], p0.y + acc[i][1],
                                     p0.z + acc[i][2], p0.w + acc[i][3]);
                dst[1] = make_float4(p1.x + acc[i][4], p1.y + acc[i][5],
                                     p1.z + acc[i][6], p1.w + acc[i][7]);
            }
        }
    }
}

// ---------------------------------------------------------------------------
extern "C" void kernel_launch(void* const* d_in, const int* in_sizes, int n_in,
                              void* d_out, int out_size) {
    const float* features = (const float*)d_in[0];
    const int*   src      = (const int*)d_in[1];
    const int*   dst      = (const int*)d_in[2];
    const float* W1       = (const float*)d_in[3];
    const float* b1       = (const float*)d_in[4];
    const float* W2       = (const float*)d_in[5];
    const float* b2       = (const float*)d_in[6];
    float* out = (float*)d_out;

    int n = in_sizes[0] / IN_FEATS;   // 50000
    int e = in_sizes[1];              // 800000
    int nb = (n + 255) / 256;         // 196

    // node-range halves (h0 multiple of 128 for clean GEMM tiles)
    int h0 = ((n / 2) + 127) / 128 * 128;
    if (h0 > n) h0 = n;
    int h1 = n - h0;
    int gb0 = (h0 + 127) / 128, gb1 = (h1 + 127) / 128;
    int sb0 = (h0 + 7) / 8,     sb1 = (h1 + 7) / 8;

    cudaStream_t sA;
    cudaStreamCreateWithFlags(&sA, cudaStreamNonBlocking);
    cudaEvent_t e0, eA, eG, eS00, eS01, eS10, eS11, eZ;
    cudaEventCreateWithFlags(&e0,   cudaEventDisableTiming);
    cudaEventCreateWithFlags(&eA,   cudaEventDisableTiming);
    cudaEventCreateWithFlags(&eG,   cudaEventDisableTiming);
    cudaEventCreateWithFlags(&eS00, cudaEventDisableTiming);
    cudaEventCreateWithFlags(&eS01, cudaEventDisableTiming);
    cudaEventCreateWithFlags(&eS10, cudaEventDisableTiming);
    cudaEventCreateWithFlags(&eS11, cudaEventDisableTiming);
    cudaEventCreateWithFlags(&eZ,   cudaEventDisableTiming);

    cudaEventRecord(e0, 0);
    cudaStreamWaitEvent(sA, e0, 0);

    // --- side stream: CSR build chain (scalar count/fill: measured best) ---
    void* cnt_ptr = nullptr;
    cudaGetSymbolAddress(&cnt_ptr, g_cnt);
    cudaMemsetAsync(cnt_ptr, 0, (size_t)n * sizeof(int), sA);
    count_kernel<<<(e + 255) / 256, 256, 0, sA>>>(dst, e);
    scan1_kernel<<<nb, 256, 0, sA>>>(n);
    scan3_kernel<<<nb, 256, 0, sA>>>(n, e, nb);
    fill_kernel<<<(e + 255) / 256, 256, 0, sA>>>(src, dst, e);
    cudaEventRecord(eA, sA);

    // --- main stream: dense prologue ---
    gemm1_kernel<<<(n + 127) / 128, 256>>>(features, W1, b1, n);
    buildM_kernel<<<(HF * 192 + 255) / 256, 256>>>(W2);
    cudaEventRecord(eG, 0);   // g_x, g_M ready

    // --- main stream: spmm halves, pipelined ---
    cudaStreamWaitEvent(0, eA, 0);
    spmm_kernel<<<sb0, 256>>>(0, h0, 0);   cudaEventRecord(eS00, 0);
    spmm_kernel<<<sb1, 256>>>(h0, h1, 0);  cudaEventRecord(eS01, 0);
    spmm_kernel<<<sb0, 256>>>(0, h0, 1);   cudaEventRecord(eS10, 0);
    spmm_kernel<<<sb1, 256>>>(h0, h1, 1);  cudaEventRecord(eS11, 0);

    // --- side stream: epilogue passes, each hidden under a spmm half ---
    cudaStreamWaitEvent(sA, eG, 0);
    gemm2_pass_kernel<<<(n + 127) / 128, 256, 0, sA>>>(b2, out, 0, n, 0);
    cudaStreamWaitEvent(sA, eS00, 0);
    gemm2_pass_kernel<<<gb0, 256, 0, sA>>>(b2, out, 0, h0, 1);
    cudaStreamWaitEvent(sA, eS01, 0);
    gemm2_pass_kernel<<<gb1, 256, 0, sA>>>(b2, out, h0, h1, 1);
    cudaStreamWaitEvent(sA, eS10, 0);
    gemm2_pass_kernel<<<gb0, 256, 0, sA>>>(b2, out, 0, h0, 2);
    cudaStreamWaitEvent(sA, eS11, 0);
    gemm2_pass_kernel<<<gb1, 256, 0, sA>>>(b2, out, h0, h1, 2);
    cudaEventRecord(eZ, sA);

    // join side -> main (capture stream must own the final dependency)
    cudaStreamWaitEvent(0, eZ, 0);

    cudaEventDestroy(e0);
    cudaEventDestroy(eA);
    cudaEventDestroy(eG);
    cudaEventDestroy(eS00);
    cudaEventDestroy(eS01);
    cudaEventDestroy(eS10);
    cudaEventDestroy(eS11);
    cudaEventDestroy(eZ);
    cudaStreamDestroy(sA);
}

// round 14
// speedup vs baseline: 1.0903x; 1.0903x over previous
#include <cuda_runtime.h>

#define N_MAX 50000
#define E_MAX 800000
#define IN_FEATS 128
#define HF 64

// Scratch (device globals; no allocation allowed)
__device__ int   g_cnt[N_MAX];
__device__ int   g_off[N_MAX + 1];
__device__ int   g_cur[N_MAX];
__device__ int   g_bsum[256];
__device__ int   g_esrc[E_MAX];
__device__ float g_dinv[N_MAX];
__device__ float g_x[N_MAX * HF];
__device__ float g_f1[N_MAX * HF];
__device__ float g_f2[N_MAX * HF];
__device__ float g_M[HF * 192];

// ---------------------------------------------------------------------------
// count: 4 edges per thread (part of the 155.8us-measured config)
__global__ void count_kernel(const int* __restrict__ dst, int e) {
    int i = (blockIdx.x * blockDim.x + threadIdx.x) * 4;
    if (i + 3 < e) {
        int4 d = *reinterpret_cast<const int4*>(dst + i);
        atomicAdd(&g_cnt[d.x], 1);
        atomicAdd(&g_cnt[d.y], 1);
        atomicAdd(&g_cnt[d.z], 1);
        atomicAdd(&g_cnt[d.w], 1);
    } else {
        for (; i < e; i++) atomicAdd(&g_cnt[dst[i]], 1);
    }
}

__global__ void scan1_kernel(int n) {
    __shared__ int sh[256];
    int t = threadIdx.x;
    int i = blockIdx.x * 256 + t;
    int v = (i < n) ? g_cnt[i] : 0;
    sh[t] = v;
    __syncthreads();
#pragma unroll
    for (int o = 1; o < 256; o <<= 1) {
        int add = (t >= o) ? sh[t - o] : 0;
        __syncthreads();
        sh[t] += add;
        __syncthreads();
    }
    if (i < n) g_off[i] = sh[t] - v;
    if (t == 255) g_bsum[blockIdx.x] = sh[255];
}

__global__ void scan3_kernel(int n, int e, int nb) {
    __shared__ int sh[256];
    int t = threadIdx.x;
    sh[t] = (t < nb) ? g_bsum[t] : 0;
    __syncthreads();
#pragma unroll
    for (int o = 1; o < 256; o <<= 1) {
        int add = (t >= o) ? sh[t - o] : 0;
        __syncthreads();
        sh[t] += add;
        __syncthreads();
    }
    int boff = (blockIdx.x == 0) ? 0 : sh[blockIdx.x - 1];
    int i = blockIdx.x * 256 + t;
    if (i < n) {
        int o = g_off[i] + boff;
        g_off[i] = o;
        g_cur[i] = o;
        g_dinv[i] = rsqrtf(fmaxf((float)g_cnt[i], 1.0f));
    }
    if (i == 0) g_off[n] = e;
}

// fill: scalar (measured faster than int4 variant: 15.1 vs 16.4 us)
__global__ void fill_kernel(const int* __restrict__ src,
                            const int* __restrict__ dst, int e) {
    int i = blockIdx.x * blockDim.x + threadIdx.x;
    if (i < e) {
        int d = dst[i];
        int pos = atomicAdd(&g_cur[d], 1);
        g_esrc[pos] = src[i];
    }
}

// ---------------------------------------------------------------------------
// Gather SpMM: fout[d] = fin[d] - dinv[d] * sum_{s in N(d)} dinv[s]*fin[s]
// NEW layout: 8 lanes per edge (each lane holds 2 adjacent float4s = 8 floats),
// FOUR independent edge streams per warp (quad = lane>>3) => 8 outstanding
// LDG.128 per warp. Final reduction: shfl_xor 8 then 16.
__global__ __launch_bounds__(256) void spmm_kernel(int n, int step) {
    const float* fin = (step == 0) ? g_x : g_f1;
    float* fout      = (step == 0) ? g_f1 : g_f2;
    int w = (blockIdx.x * blockDim.x + threadIdx.x) >> 5;
    int lane = threadIdx.x & 31;
    if (w >= n) return;
    int c8 = lane & 7;        // feature octet: floats [c8*8, c8*8+8)
    int quad = lane >> 3;     // edge stream 0..3
    int beg = g_off[w];
    int end = g_off[w + 1];
    const float4* F4 = reinterpret_cast<const float4*>(fin);
    float4 accA = make_float4(0.f, 0.f, 0.f, 0.f);
    float4 accB = make_float4(0.f, 0.f, 0.f, 0.f);

    int j = beg + quad;       // this stream handles j, j+4, j+8, ...
    int s_next = (j < end) ? __ldg(&g_esrc[j]) : 0;
    while (j < end) {
        int s = s_next;
        int jn = j + 4;
        if (jn < end) s_next = __ldg(&g_esrc[jn]);
        float wt = __ldg(&g_dinv[s]);
        float4 vA = F4[(size_t)s * 16 + c8 * 2];
        float4 vB = F4[(size_t)s * 16 + c8 * 2 + 1];
        accA.x = fmaf(wt, vA.x, accA.x);
        accA.y = fmaf(wt, vA.y, accA.y);
        accA.z = fmaf(wt, vA.z, accA.z);
        accA.w = fmaf(wt, vA.w, accA.w);
        accB.x = fmaf(wt, vB.x, accB.x);
        accB.y = fmaf(wt, vB.y, accB.y);
        accB.z = fmaf(wt, vB.z, accB.z);
        accB.w = fmaf(wt, vB.w, accB.w);
        j = jn;
    }

    // reduce across the 4 quads (lanes L, L^8, L^16, L^24 share octet c8)
#pragma unroll
    for (int off = 8; off <= 16; off <<= 1) {
        accA.x += __shfl_xor_sync(0xffffffffu, accA.x, off);
        accA.y += __shfl_xor_sync(0xffffffffu, accA.y, off);
        accA.z += __shfl_xor_sync(0xffffffffu, accA.z, off);
        accA.w += __shfl_xor_sync(0xffffffffu, accA.w, off);
        accB.x += __shfl_xor_sync(0xffffffffu, accB.x, off);
        accB.y += __shfl_xor_sync(0xffffffffu, accB.y, off);
        accB.z += __shfl_xor_sync(0xffffffffu, accB.z, off);
        accB.w += __shfl_xor_sync(0xffffffffu, accB.w, off);
    }

    if (quad == 0) {
        float wd = g_dinv[w];
        float4 xA = F4[(size_t)w * 16 + c8 * 2];
        float4 xB = F4[(size_t)w * 16 + c8 * 2 + 1];
        float4* O = reinterpret_cast<float4*>(fout);
        O[(size_t)w * 16 + c8 * 2] =
            make_float4(xA.x - wd * accA.x, xA.y - wd * accA.y,
                        xA.z - wd * accA.z, xA.w - wd * accA.w);
        O[(size_t)w * 16 + c8 * 2 + 1] =
            make_float4(xB.x - wd * accB.x, xB.y - wd * accB.y,
                        xB.z - wd * accB.z, xB.w - wd * accB.w);
    }
}

// ---------------------------------------------------------------------------
// GEMM1 (best-measured version, unchanged)
__global__ __launch_bounds__(256) void gemm1_kernel(
    const float* __restrict__ A, const float* __restrict__ W1,
    const float* __restrict__ b1, int n) {
    __shared__ float As[32][132];
    __shared__ float Bs[32][68];
    int t = threadIdx.x;
    int m0 = blockIdx.x * 128;
    int tx = t & 7, ty = t >> 3;
    int kv = t & 7, m4 = t >> 3;

    float acc[4][8];
#pragma unroll
    for (int i = 0; i < 4; i++)
#pragma unroll
        for (int j = 0; j < 8; j++) acc[i][j] = 0.f;

    for (int k0 = 0; k0 < IN_FEATS; k0 += 32) {
#pragma unroll
        for (int i = 0; i < 4; i++) {
            int m = m4 * 4 + i;
            int gm = m0 + m;
            float4 v = make_float4(0.f, 0.f, 0.f, 0.f);
            if (gm < n)
                v = *reinterpret_cast<const float4*>(A + (size_t)gm * IN_FEATS + k0 + kv * 4);
            As[kv * 4 + 0][m] = v.x;
            As[kv * 4 + 1][m] = v.y;
            As[kv * 4 + 2][m] = v.z;
            As[kv * 4 + 3][m] = v.w;
        }
#pragma unroll
        for (int i = 0; i < 2; i++) {
            int fl = t * 2 + i;
            int nn = fl >> 3, kv2 = fl & 7;
            float4 v = *reinterpret_cast<const float4*>(W1 + (size_t)nn * IN_FEATS + k0 + kv2 * 4);
            Bs[kv2 * 4 + 0][nn] = v.x;
            Bs[kv2 * 4 + 1][nn] = v.y;
            Bs[kv2 * 4 + 2][nn] = v.z;
            Bs[kv2 * 4 + 3][nn] = v.w;
        }
        __syncthreads();
#pragma unroll
        for (int k = 0; k < 32; k++) {
            float4 a = *reinterpret_cast<float4*>(&As[k][ty * 4]);
            float4 bA = *reinterpret_cast<float4*>(&Bs[k][tx * 8]);
            float4 bB = *reinterpret_cast<float4*>(&Bs[k][tx * 8 + 4]);
            float av[4] = {a.x, a.y, a.z, a.w};
            float bv[8] = {bA.x, bA.y, bA.z, bA.w, bB.x, bB.y, bB.z, bB.w};
#pragma unroll
            for (int i = 0; i < 4; i++)
#pragma unroll
                for (int j = 0; j < 8; j++)
                    acc[i][j] = fmaf(av[i], bv[j], acc[i][j]);
        }
        __syncthreads();
    }
#pragma unroll
    for (int i = 0; i < 4; i++) {
        int gm = m0 + ty * 4 + i;
        if (gm < n) {
#pragma unroll
            for (int j = 0; j < 8; j++) {
                float v = acc[i][j] + b1[tx * 8 + j];
                g_x[(size_t)gm * HF + tx * 8 + j] = v > 0.f ? v : 0.f;
            }
        }
    }
}

// ---------------------------------------------------------------------------
__global__ void buildM_kernel(const float* __restrict__ W2) {
    int t = blockIdx.x * blockDim.x + threadIdx.x;
    if (t >= HF * 192) return;
    int r = t / 192, k = t % 192;
    int p = k >> 6, c = k & 63;
    const float cA[3] = {3.0f, -3.0f, 0.75f};
    const float cB[3] = {0.0f, 3.0f, -1.5f};
    const float cC[3] = {0.0f, 0.0f, 0.75f};
    g_M[t] = cA[p] * W2[r * 192 + c]
           + cB[p] * W2[r * 192 + 64 + c]
           + cC[p] * W2[r * 192 + 128 + c];
}

// ---------------------------------------------------------------------------
// GEMM2 rank-64 pass (R12 version, full-range, unchanged)
__global__ __launch_bounds__(256) void gemm2_pass_kernel(
    const float* __restrict__ b2, float* __restrict__ out, int n, int pass) {
    __shared__ float As[32][132];
    __shared__ float Bs[32][68];
    int t = threadIdx.x;
    int m0 = blockIdx.x * 128;
    int tx = t & 7, ty = t >> 3;
    int kv = t & 7, m4 = t >> 3;
    const float* S = (pass == 0) ? g_x : (pass == 1) ? g_f1 : g_f2;

    float acc[4][8];
#pragma unroll
    for (int i = 0; i < 4; i++)
#pragma unroll
        for (int j = 0; j < 8; j++) acc[i][j] = 0.f;

#pragma unroll
    for (int cch = 0; cch < 2; cch++) {
        int koff = cch * 32;
#pragma unroll
        for (int i = 0; i < 4; i++) {
            int m = m4 * 4 + i;
            int gm = m0 + m;
            float4 v = make_float4(0.f, 0.f, 0.f, 0.f);
            if (gm < n)
                v = *reinterpret_cast<const float4*>(S + (size_t)gm * HF + koff + kv * 4);
            As[kv * 4 + 0][m] = v.x;
            As[kv * 4 + 1][m] = v.y;
            As[kv * 4 + 2][m] = v.z;
            As[kv * 4 + 3][m] = v.w;
        }
#pragma unroll
        for (int i = 0; i < 2; i++) {
            int fl = t * 2 + i;
            int nn = fl >> 3, kv2 = fl & 7;
            float4 v = *reinterpret_cast<const float4*>(
                g_M + (size_t)nn * 192 + pass * 64 + koff + kv2 * 4);
            Bs[kv2 * 4 + 0][nn] = v.x;
            Bs[kv2 * 4 + 1][nn] = v.y;
            Bs[kv2 * 4 + 2][nn] = v.z;
            Bs[kv2 * 4 + 3][nn] = v.w;
        }
        __syncthreads();
#pragma unroll
        for (int k = 0; k < 32; k++) {
            float4 a = *reinterpret_cast<float4*>(&As[k][ty * 4]);
            float4 bA = *reinterpret_cast<float4*>(&Bs[k][tx * 8]);
            float4 bB = *reinterpret_cast<float4*>(&Bs[k][tx * 8 + 4]);
            float av[4] = {a.x, a.y, a.z, a.w};
            float bv[8] = {bA.x, bA.y, bA.z, bA.w, bB.x, bB.y, bB.z, bB.w};
#pragma unroll
            for (int i = 0; i < 4; i++)
#pragma unroll
                for (int j = 0; j < 8; j++)
                    acc[i][j] = fmaf(av[i], bv[j], acc[i][j]);
        }
        __syncthreads();
    }
#pragma unroll
    for (int i = 0; i < 4; i++) {
        int gm = m0 + ty * 4 + i;
        if (gm < n) {
            float4* dst = reinterpret_cast<float4*>(&out[(size_t)gm * HF + tx * 8]);
            if (pass == 0) {
                float o[8];
#pragma unroll
                for (int j = 0; j < 8; j++) o[j] = acc[i][j] + b2[tx * 8 + j];
                dst[0] = make_float4(o[0], o[1], o[2], o[3]);
                dst[1] = make_float4(o[4], o[5], o[6], o[7]);
            } else {
                float4 p0 = dst[0], p1 = dst[1];
                dst[0] = make_float4(p0.x + acc[i][0], p0.y + acc[i][1],
                                     p0.z + acc[i][2], p0.w + acc[i][3]);
                dst[1] = make_float4(p1.x + acc[i][4], p1.y + acc[i][5],
                                     p1.z + acc[i][6], p1.w + acc[i][7]);
            }
        }
    }
}

// ---------------------------------------------------------------------------
extern "C" void kernel_launch(void* const* d_in, const int* in_sizes, int n_in,
                              void* d_out, int out_size) {
    const float* features = (const float*)d_in[0];
    const int*   src      = (const int*)d_in[1];
    const int*   dst      = (const int*)d_in[2];
    const float* W1       = (const float*)d_in[3];
    const float* b1       = (const float*)d_in[4];
    const float* W2       = (const float*)d_in[5];
    const float* b2       = (const float*)d_in[6];
    float* out = (float*)d_out;

    int n = in_sizes[0] / IN_FEATS;   // 50000
    int e = in_sizes[1];              // 800000
    int nb = (n + 255) / 256;         // 196
    int gb = (n + 127) / 128;         // GEMM grid
    int eb4 = (e / 4 + 255) / 256;    // vectorized count

    cudaStream_t sA;
    cudaStreamCreateWithFlags(&sA, cudaStreamNonBlocking);
    cudaEvent_t e0, eA, eG, eS0, eB;
    cudaEventCreateWithFlags(&e0,  cudaEventDisableTiming);
    cudaEventCreateWithFlags(&eA,  cudaEventDisableTiming);
    cudaEventCreateWithFlags(&eG,  cudaEventDisableTiming);
    cudaEventCreateWithFlags(&eS0, cudaEventDisableTiming);
    cudaEventCreateWithFlags(&eB,  cudaEventDisableTiming);

    cudaEventRecord(e0, 0);
    cudaStreamWaitEvent(sA, e0, 0);

    // --- side stream: CSR build chain ---
    void* cnt_ptr = nullptr;
    cudaGetSymbolAddress(&cnt_ptr, g_cnt);
    cudaMemsetAsync(cnt_ptr, 0, (size_t)n * sizeof(int), sA);
    count_kernel<<<eb4, 256, 0, sA>>>(dst, e);
    scan1_kernel<<<nb, 256, 0, sA>>>(n);
    scan3_kernel<<<nb, 256, 0, sA>>>(n, e, nb);
    fill_kernel<<<(e + 255) / 256, 256, 0, sA>>>(src, dst, e);
    cudaEventRecord(eA, sA);

    // --- main stream: dense prologue ---
    gemm1_kernel<<<gb, 256>>>(features, W1, b1, n);
    buildM_kernel<<<(HF * 192 + 255) / 256, 256>>>(W2);
    cudaEventRecord(eG, 0);   // g_x and g_M ready

    // join: spmm0 needs g_x and CSR
    cudaStreamWaitEvent(0, eA, 0);
    int spmm_blocks = (n + 7) / 8;
    spmm_kernel<<<spmm_blocks, 256>>>(n, 0);         // f1 = L x
    cudaEventRecord(eS0, 0);

    // side stream: pass0 concurrent with spmm0, pass1 concurrent with spmm1
    cudaStreamWaitEvent(sA, eG, 0);
    gemm2_pass_kernel<<<gb, 256, 0, sA>>>(b2, out, n, 0);
    cudaStreamWaitEvent(sA, eS0, 0);
    gemm2_pass_kernel<<<gb, 256, 0, sA>>>(b2, out, n, 1);
    cudaEventRecord(eB, sA);

    // main stream: spmm1 (f2 = L f1)
    spmm_kernel<<<spmm_blocks, 256>>>(n, 1);

    // tail: pass2 needs f2 (main) and out from pass1 (side)
    cudaStreamWaitEvent(0, eB, 0);
    gemm2_pass_kernel<<<gb, 256>>>(b2, out, n, 2);   // out += f2*M2^T

    cudaEventDestroy(e0);
    cudaEventDestroy(eA);
    cudaEventDestroy(eG);
    cudaEventDestroy(eS0);
    cudaEventDestroy(eB);
    cudaStreamDestroy(sA);
}

// round 15
// speedup vs baseline: 1.1759x; 1.0785x over previous
#include <cuda_runtime.h>

#define N_MAX 50000
#define E_MAX 800000
#define IN_FEATS 128
#define HF 64

// Scratch (device globals; no allocation allowed)
__device__ int   g_cnt[N_MAX];
__device__ int   g_off[N_MAX + 1];
__device__ int   g_cur[N_MAX];
__device__ int   g_bsum[256];
__device__ int   g_esrc[E_MAX];
__device__ float g_dinv[N_MAX];
__device__ float g_x[N_MAX * HF];
__device__ float g_f1[N_MAX * HF];
__device__ float g_f2[N_MAX * HF];
__device__ float g_M[HF * 192];

// ---------------------------------------------------------------------------
// count: 4 edges per thread (part of the 155.8us-measured config)
__global__ void count_kernel(const int* __restrict__ dst, int e) {
    int i = (blockIdx.x * blockDim.x + threadIdx.x) * 4;
    if (i + 3 < e) {
        int4 d = *reinterpret_cast<const int4*>(dst + i);
        atomicAdd(&g_cnt[d.x], 1);
        atomicAdd(&g_cnt[d.y], 1);
        atomicAdd(&g_cnt[d.z], 1);
        atomicAdd(&g_cnt[d.w], 1);
    } else {
        for (; i < e; i++) atomicAdd(&g_cnt[dst[i]], 1);
    }
}

__global__ void scan1_kernel(int n) {
    __shared__ int sh[256];
    int t = threadIdx.x;
    int i = blockIdx.x * 256 + t;
    int v = (i < n) ? g_cnt[i] : 0;
    sh[t] = v;
    __syncthreads();
#pragma unroll
    for (int o = 1; o < 256; o <<= 1) {
        int add = (t >= o) ? sh[t - o] : 0;
        __syncthreads();
        sh[t] += add;
        __syncthreads();
    }
    if (i < n) g_off[i] = sh[t] - v;
    if (t == 255) g_bsum[blockIdx.x] = sh[255];
}

__global__ void scan3_kernel(int n, int e, int nb) {
    __shared__ int sh[256];
    int t = threadIdx.x;
    sh[t] = (t < nb) ? g_bsum[t] : 0;
    __syncthreads();
#pragma unroll
    for (int o = 1; o < 256; o <<= 1) {
        int add = (t >= o) ? sh[t - o] : 0;
        __syncthreads();
        sh[t] += add;
        __syncthreads();
    }
    int boff = (blockIdx.x == 0) ? 0 : sh[blockIdx.x - 1];
    int i = blockIdx.x * 256 + t;
    if (i < n) {
        int o = g_off[i] + boff;
        g_off[i] = o;
        g_cur[i] = o;
        g_dinv[i] = rsqrtf(fmaxf((float)g_cnt[i], 1.0f));
    }
    if (i == 0) g_off[n] = e;
}

// fill: scalar (measured 15.1us vs 16.4us for the int4 variant)
__global__ void fill_kernel(const int* __restrict__ src,
                            const int* __restrict__ dst, int e) {
    int i = blockIdx.x * blockDim.x + threadIdx.x;
    if (i < e) {
        int d = dst[i];
        int pos = atomicAdd(&g_cur[d], 1);
        g_esrc[pos] = src[i];
    }
}

// ---------------------------------------------------------------------------
// Gather SpMM (R12 measured-best layout: 16 lanes/edge float4, 2 edges in
// flight per warp, next-index prefetch, shfl_xor(16) reduction).
// Delta vs R12: feature loads via __ldg (LDG.CI -> L1-resident read path).
__global__ __launch_bounds__(256) void spmm_kernel(int n, int step) {
    const float* fin = (step == 0) ? g_x : g_f1;
    float* fout      = (step == 0) ? g_f1 : g_f2;
    int w = (blockIdx.x * blockDim.x + threadIdx.x) >> 5;
    int lane = threadIdx.x & 31;
    if (w >= n) return;
    int c = lane & 15;
    int pair = lane >> 4;
    int beg = g_off[w];
    int end = g_off[w + 1];
    const float4* F4 = reinterpret_cast<const float4*>(fin);
    float4 acc = make_float4(0.f, 0.f, 0.f, 0.f);

    int j = beg + pair;
    int s_next = (j < end) ? __ldg(&g_esrc[j]) : 0;
    while (j < end) {
        int s = s_next;
        int jn = j + 2;
        if (jn < end) s_next = __ldg(&g_esrc[jn]);
        float wt = __ldg(&g_dinv[s]);
        float4 v = __ldg(&F4[(size_t)s * 16 + c]);
        acc.x = fmaf(wt, v.x, acc.x);
        acc.y = fmaf(wt, v.y, acc.y);
        acc.z = fmaf(wt, v.z, acc.z);
        acc.w = fmaf(wt, v.w, acc.w);
        j = jn;
    }

    acc.x += __shfl_xor_sync(0xffffffffu, acc.x, 16);
    acc.y += __shfl_xor_sync(0xffffffffu, acc.y, 16);
    acc.z += __shfl_xor_sync(0xffffffffu, acc.z, 16);
    acc.w += __shfl_xor_sync(0xffffffffu, acc.w, 16);

    if (pair == 0) {
        float wd = g_dinv[w];
        float4 xv = __ldg(&F4[(size_t)w * 16 + c]);
        float4 r = make_float4(xv.x - wd * acc.x, xv.y - wd * acc.y,
                               xv.z - wd * acc.z, xv.w - wd * acc.w);
        reinterpret_cast<float4*>(fout)[(size_t)w * 16 + c] = r;
    }
}

// ---------------------------------------------------------------------------
// GEMM1 (best-measured version, unchanged)
__global__ __launch_bounds__(256) void gemm1_kernel(
    const float* __restrict__ A, const float* __restrict__ W1,
    const float* __restrict__ b1, int n) {
    __shared__ float As[32][132];
    __shared__ float Bs[32][68];
    int t = threadIdx.x;
    int m0 = blockIdx.x * 128;
    int tx = t & 7, ty = t >> 3;
    int kv = t & 7, m4 = t >> 3;

    float acc[4][8];
#pragma unroll
    for (int i = 0; i < 4; i++)
#pragma unroll
        for (int j = 0; j < 8; j++) acc[i][j] = 0.f;

    for (int k0 = 0; k0 < IN_FEATS; k0 += 32) {
#pragma unroll
        for (int i = 0; i < 4; i++) {
            int m = m4 * 4 + i;
            int gm = m0 + m;
            float4 v = make_float4(0.f, 0.f, 0.f, 0.f);
            if (gm < n)
                v = *reinterpret_cast<const float4*>(A + (size_t)gm * IN_FEATS + k0 + kv * 4);
            As[kv * 4 + 0][m] = v.x;
            As[kv * 4 + 1][m] = v.y;
            As[kv * 4 + 2][m] = v.z;
            As[kv * 4 + 3][m] = v.w;
        }
#pragma unroll
        for (int i = 0; i < 2; i++) {
            int fl = t * 2 + i;
            int nn = fl >> 3, kv2 = fl & 7;
            float4 v = *reinterpret_cast<const float4*>(W1 + (size_t)nn * IN_FEATS + k0 + kv2 * 4);
            Bs[kv2 * 4 + 0][nn] = v.x;
            Bs[kv2 * 4 + 1][nn] = v.y;
            Bs[kv2 * 4 + 2][nn] = v.z;
            Bs[kv2 * 4 + 3][nn] = v.w;
        }
        __syncthreads();
#pragma unroll
        for (int k = 0; k < 32; k++) {
            float4 a = *reinterpret_cast<float4*>(&As[k][ty * 4]);
            float4 bA = *reinterpret_cast<float4*>(&Bs[k][tx * 8]);
            float4 bB = *reinterpret_cast<float4*>(&Bs[k][tx * 8 + 4]);
            float av[4] = {a.x, a.y, a.z, a.w};
            float bv[8] = {bA.x, bA.y, bA.z, bA.w, bB.x, bB.y, bB.z, bB.w};
#pragma unroll
            for (int i = 0; i < 4; i++)
#pragma unroll
                for (int j = 0; j < 8; j++)
                    acc[i][j] = fmaf(av[i], bv[j], acc[i][j]);
        }
        __syncthreads();
    }
#pragma unroll
    for (int i = 0; i < 4; i++) {
        int gm = m0 + ty * 4 + i;
        if (gm < n) {
#pragma unroll
            for (int j = 0; j < 8; j++) {
                float v = acc[i][j] + b1[tx * 8 + j];
                g_x[(size_t)gm * HF + tx * 8 + j] = v > 0.f ? v : 0.f;
            }
        }
    }
}

// ---------------------------------------------------------------------------
__global__ void buildM_kernel(const float* __restrict__ W2) {
    int t = blockIdx.x * blockDim.x + threadIdx.x;
    if (t >= HF * 192) return;
    int r = t / 192, k = t % 192;
    int p = k >> 6, c = k & 63;
    const float cA[3] = {3.0f, -3.0f, 0.75f};
    const float cB[3] = {0.0f, 3.0f, -1.5f};
    const float cC[3] = {0.0f, 0.0f, 0.75f};
    g_M[t] = cA[p] * W2[r * 192 + c]
           + cB[p] * W2[r * 192 + 64 + c]
           + cC[p] * W2[r * 192 + 128 + c];
}

// ---------------------------------------------------------------------------
// GEMM2 rank-64 pass (R12 version, unchanged)
__global__ __launch_bounds__(256) void gemm2_pass_kernel(
    const float* __restrict__ b2, float* __restrict__ out, int n, int pass) {
    __shared__ float As[32][132];
    __shared__ float Bs[32][68];
    int t = threadIdx.x;
    int m0 = blockIdx.x * 128;
    int tx = t & 7, ty = t >> 3;
    int kv = t & 7, m4 = t >> 3;
    const float* S = (pass == 0) ? g_x : (pass == 1) ? g_f1 : g_f2;

    float acc[4][8];
#pragma unroll
    for (int i = 0; i < 4; i++)
#pragma unroll
        for (int j = 0; j < 8; j++) acc[i][j] = 0.f;

#pragma unroll
    for (int cch = 0; cch < 2; cch++) {
        int koff = cch * 32;
#pragma unroll
        for (int i = 0; i < 4; i++) {
            int m = m4 * 4 + i;
            int gm = m0 + m;
            float4 v = make_float4(0.f, 0.f, 0.f, 0.f);
            if (gm < n)
                v = *reinterpret_cast<const float4*>(S + (size_t)gm * HF + koff + kv * 4);
            As[kv * 4 + 0][m] = v.x;
            As[kv * 4 + 1][m] = v.y;
            As[kv * 4 + 2][m] = v.z;
            As[kv * 4 + 3][m] = v.w;
        }
#pragma unroll
        for (int i = 0; i < 2; i++) {
            int fl = t * 2 + i;
            int nn = fl >> 3, kv2 = fl & 7;
            float4 v = *reinterpret_cast<const float4*>(
                g_M + (size_t)nn * 192 + pass * 64 + koff + kv2 * 4);
            Bs[kv2 * 4 + 0][nn] = v.x;
            Bs[kv2 * 4 + 1][nn] = v.y;
            Bs[kv2 * 4 + 2][nn] = v.z;
            Bs[kv2 * 4 + 3][nn] = v.w;
        }
        __syncthreads();
#pragma unroll
        for (int k = 0; k < 32; k++) {
            float4 a = *reinterpret_cast<float4*>(&As[k][ty * 4]);
            float4 bA = *reinterpret_cast<float4*>(&Bs[k][tx * 8]);
            float4 bB = *reinterpret_cast<float4*>(&Bs[k][tx * 8 + 4]);
            float av[4] = {a.x, a.y, a.z, a.w};
            float bv[8] = {bA.x, bA.y, bA.z, bA.w, bB.x, bB.y, bB.z, bB.w};
#pragma unroll
            for (int i = 0; i < 4; i++)
#pragma unroll
                for (int j = 0; j < 8; j++)
                    acc[i][j] = fmaf(av[i], bv[j], acc[i][j]);
        }
        __syncthreads();
    }
#pragma unroll
    for (int i = 0; i < 4; i++) {
        int gm = m0 + ty * 4 + i;
        if (gm < n) {
            float4* dst = reinterpret_cast<float4*>(&out[(size_t)gm * HF + tx * 8]);
            if (pass == 0) {
                float o[8];
#pragma unroll
                for (int j = 0; j < 8; j++) o[j] = acc[i][j] + b2[tx * 8 + j];
                dst[0] = make_float4(o[0], o[1], o[2], o[3]);
                dst[1] = make_float4(o[4], o[5], o[6], o[7]);
            } else {
                float4 p0 = dst[0], p1 = dst[1];
                dst[0] = make_float4(p0.x + acc[i][0], p0.y + acc[i][1],
                                     p0.z + acc[i][2], p0.w + acc[i][3]);
                dst[1] = make_float4(p1.x + acc[i][4], p1.y + acc[i][5],
                                     p1.z + acc[i][6], p1.w + acc[i][7]);
            }
        }
    }
}

// ---------------------------------------------------------------------------
extern "C" void kernel_launch(void* const* d_in, const int* in_sizes, int n_in,
                              void* d_out, int out_size) {
    const float* features = (const float*)d_in[0];
    const int*   src      = (const int*)d_in[1];
    const int*   dst      = (const int*)d_in[2];
    const float* W1       = (const float*)d_in[3];
    const float* b1       = (const float*)d_in[4];
    const float* W2       = (const float*)d_in[5];
    const float* b2       = (const float*)d_in[6];
    float* out = (float*)d_out;

    int n = in_sizes[0] / IN_FEATS;   // 50000
    int e = in_sizes[1];              // 800000
    int nb = (n + 255) / 256;         // 196
    int gb = (n + 127) / 128;         // GEMM grid
    int eb4 = (e / 4 + 255) / 256;    // vectorized count

    cudaStream_t sA;
    cudaStreamCreateWithFlags(&sA, cudaStreamNonBlocking);
    cudaEvent_t e0, eA, eG, eS0, eB;
    cudaEventCreateWithFlags(&e0,  cudaEventDisableTiming);
    cudaEventCreateWithFlags(&eA,  cudaEventDisableTiming);
    cudaEventCreateWithFlags(&eG,  cudaEventDisableTiming);
    cudaEventCreateWithFlags(&eS0, cudaEventDisableTiming);
    cudaEventCreateWithFlags(&eB,  cudaEventDisableTiming);

    cudaEventRecord(e0, 0);
    cudaStreamWaitEvent(sA, e0, 0);

    // --- side stream: CSR build chain ---
    void* cnt_ptr = nullptr;
    cudaGetSymbolAddress(&cnt_ptr, g_cnt);
    cudaMemsetAsync(cnt_ptr, 0, (size_t)n * sizeof(int), sA);
    count_kernel<<<eb4, 256, 0, sA>>>(dst, e);
    scan1_kernel<<<nb, 256, 0, sA>>>(n);
    scan3_kernel<<<nb, 256, 0, sA>>>(n, e, nb);
    fill_kernel<<<(e + 255) / 256, 256, 0, sA>>>(src, dst, e);
    cudaEventRecord(eA, sA);

    // --- main stream: dense prologue ---
    gemm1_kernel<<<gb, 256>>>(features, W1, b1, n);
    buildM_kernel<<<(HF * 192 + 255) / 256, 256>>>(W2);
    cudaEventRecord(eG, 0);   // g_x and g_M ready

    // join: spmm0 needs g_x and CSR
    cudaStreamWaitEvent(0, eA, 0);
    int spmm_blocks = (n + 7) / 8;
    spmm_kernel<<<spmm_blocks, 256>>>(n, 0);         // f1 = L x
    cudaEventRecord(eS0, 0);

    // side stream: pass0 concurrent with spmm0, pass1 concurrent with spmm1
    cudaStreamWaitEvent(sA, eG, 0);
    gemm2_pass_kernel<<<gb, 256, 0, sA>>>(b2, out, n, 0);
    cudaStreamWaitEvent(sA, eS0, 0);
    gemm2_pass_kernel<<<gb, 256, 0, sA>>>(b2, out, n, 1);
    cudaEventRecord(eB, sA);

    // main stream: spmm1 (f2 = L f1)
    spmm_kernel<<<spmm_blocks, 256>>>(n, 1);

    // tail: pass2 needs f2 (main) and out from pass1 (side)
    cudaStreamWaitEvent(0, eB, 0);
    gemm2_pass_kernel<<<gb, 256>>>(b2, out, n, 2);   // out += f2*M2^T

    cudaEventDestroy(e0);
    cudaEventDestroy(eA);
    cudaEventDestroy(eG);
    cudaEventDestroy(eS0);
    cudaEventDestroy(eB);
    cudaStreamDestroy(sA);
}